// round 3
// baseline (speedup 1.0000x reference)
#include <cuda_runtime.h>

// VectorQuantizer: z (8,128,4096) f32, codebook (1024,128) f32.
// Output layout (confirmed by R1 misalign signature): concatenated f32
//   [0)            z_q_out  (B,D,T)        4,194,304
//   [4194304)      codes    (B,T) as f32      32,768
//   [4227072)      loss     scalar                 1
//   [4227073)      dist     (B,T,1024)    33,554,432   <-- odd offset: NOT 16B aligned
// total 37,781,505

#define DD      128
#define NCODES  1024
#define TT      4096
#define BB      8
#define BT      (BB*TT)          // 32768
#define TM      128              // rows per CTA
#define TN      64               // codes per tile
#define NT      (NCODES/TN)      // 16
#define CS_LD   72               // padded lead dim for codebook tile
#define TPB     256

#define ZQ_ELEMS   (BB*DD*TT)    // 4194304
#define OUT_FULL   (ZQ_ELEMS + BT + 1 + (long long)BT*NCODES)

__device__ int    g_codes[BT];
__device__ double g_partial[BT/TM];   // 256 CTA partial loss sums
__device__ float  g_c2[NCODES];

// ---------------------------------------------------------------- c2 = ||c||^2
__global__ void c2_kernel(const float* __restrict__ cb) {
    int i = blockIdx.x * blockDim.x + threadIdx.x;
    if (i < NCODES) {
        const float* r = cb + (size_t)i * DD;
        double s = 0.0;
        #pragma unroll 8
        for (int d = 0; d < DD; ++d) { float v = r[d]; s += (double)v * (double)v; }
        g_c2[i] = (float)s;
    }
}

// --------------------------------------------- main: dist + argmin + loss parts
// smem: zs[128][128] f32 (64KB) | cs[128][72] f32 (36KB) | r2s[128] f32
__global__ __launch_bounds__(TPB, 2)
void dist_kernel(const float* __restrict__ z, const float* __restrict__ cb,
                 float* __restrict__ dist, float* __restrict__ codesF) {
    extern __shared__ float sm[];
    float* zs  = sm;                   // DD*TM
    float* cs  = sm + DD * TM;         // DD*CS_LD
    float* r2s = cs + DD * CS_LD;      // TM

    const int tid = threadIdx.x;
    const int bx  = blockIdx.x;            // 0..255
    const int b   = bx >> 5;               // batch
    const int t0  = (bx & 31) * TM;        // t offset within batch
    const size_t rbase = (size_t)b * TT + t0;

    // load z tile: zs[d][tloc] = z[b, d, t0+tloc]  (coalesced along t)
    const float* zb = z + (size_t)b * DD * TT + t0;
    for (int idx = tid; idx < DD * TM; idx += TPB) {
        int d = idx >> 7, tl = idx & 127;
        zs[idx] = zb[(size_t)d * TT + tl];
    }
    __syncthreads();

    // r2 per row in fp64, rounded once
    if (tid < TM) {
        double s = 0.0;
        for (int d = 0; d < DD; ++d) { float v = zs[d * TM + tid]; s += (double)v * (double)v; }
        r2s[tid] = (float)s;
    }

    const int tx = tid & 15;    // code groups of 4
    const int ty = tid >> 4;    // row groups of 8

    float bV[8]; int bI[8];
    #pragma unroll
    for (int i = 0; i < 8; ++i) { bV[i] = 3.4e38f; bI[i] = 0x7fffffff; }

    for (int jt = 0; jt < NT; ++jt) {
        const int cb0 = jt * TN;
        __syncthreads();   // prev compute done (and r2s ready on first iter)
        // load codebook tile transposed: cs[d][cloc] = cb[cb0+cloc][d]
        for (int idx = tid; idx < TN * DD; idx += TPB) {
            int cloc = idx >> 7, d = idx & 127;
            cs[d * CS_LD + cloc] = cb[(size_t)(cb0 + cloc) * DD + d];
        }
        __syncthreads();

        float acc[8][4];
        #pragma unroll
        for (int i = 0; i < 8; ++i)
            #pragma unroll
            for (int j = 0; j < 4; ++j) acc[i][j] = 0.0f;

        #pragma unroll 4
        for (int k = 0; k < DD; ++k) {
            const float4 a0 = *reinterpret_cast<const float4*>(&zs[k * TM + ty * 8]);
            const float4 a1 = *reinterpret_cast<const float4*>(&zs[k * TM + ty * 8 + 4]);
            const float4 bq = *reinterpret_cast<const float4*>(&cs[k * CS_LD + tx * 4]);
            const float av[8] = {a0.x, a0.y, a0.z, a0.w, a1.x, a1.y, a1.z, a1.w};
            const float bv[4] = {bq.x, bq.y, bq.z, bq.w};
            #pragma unroll
            for (int i = 0; i < 8; ++i)
                #pragma unroll
                for (int j = 0; j < 4; ++j)
                    acc[i][j] += av[i] * bv[j];
        }

        // epilogue: dist = (r2 - 2*dot) + c2  (exact reference association, no FMA)
        float c2v[4];
        #pragma unroll
        for (int j = 0; j < 4; ++j) c2v[j] = g_c2[cb0 + tx * 4 + j];

        #pragma unroll
        for (int i = 0; i < 8; ++i) {
            const int row = ty * 8 + i;
            const float r2 = r2s[row];
            float dsv[4];
            #pragma unroll
            for (int j = 0; j < 4; ++j) {
                float ds = __fadd_rn(__fsub_rn(r2, __fmul_rn(2.0f, acc[i][j])), c2v[j]);
                dsv[j] = ds;
                const int code = cb0 + tx * 4 + j;
                if (ds < bV[i]) { bV[i] = ds; bI[i] = code; }   // j ascending -> first index kept
            }
            if (dist) {
                // dist base is odd-float offset -> NOT 16B aligned; scalar streaming stores
                float* dp = dist + (rbase + row) * NCODES + cb0 + tx * 4;
                #pragma unroll
                for (int j = 0; j < 4; ++j) __stcs(dp + j, dsv[j]);
            }
        }
    }
    __syncthreads();

    // cross-thread argmin per row (lexicographic (val, idx) min == jnp first-index argmin)
    float* redV = cs;                          // 16*128 floats
    int*   redI = reinterpret_cast<int*>(cs + 16 * TM);
    #pragma unroll
    for (int i = 0; i < 8; ++i) {
        const int row = ty * 8 + i;
        redV[tx * TM + row] = bV[i];
        redI[tx * TM + row] = bI[i];
    }
    __syncthreads();

    double* dsum = reinterpret_cast<double*>(zs);   // reuse zs region
    if (tid < TM) {
        float bv = redV[tid]; int bi = redI[tid];
        #pragma unroll
        for (int t = 1; t < 16; ++t) {
            float v = redV[t * TM + tid]; int ii = redI[t * TM + tid];
            if (v < bv || (v == bv && ii < bi)) { bv = v; bi = ii; }
        }
        const int rg = (int)(rbase + tid);
        g_codes[rg] = bi;
        if (codesF) codesF[rg] = (float)bi;
        dsum[tid] = (double)bv;      // min dist == sum_d (z-c)^2 for loss
    }
    __syncthreads();
    for (int s = TM / 2; s > 0; s >>= 1) {
        if (tid < s) dsum[tid] += dsum[tid + s];
        __syncthreads();
    }
    if (tid == 0) g_partial[bx] = dsum[0];
}

// ------------------------------------------------------------- z_q gather (B,D,T)
__global__ void zq_kernel(const float* __restrict__ cb, float* __restrict__ zq) {
    int idx = blockIdx.x * blockDim.x + threadIdx.x;   // < 4194304
    int t = idx & (TT - 1);
    int d = (idx >> 12) & (DD - 1);
    int b = idx >> 19;
    int code = g_codes[(b << 12) + t];
    zq[idx] = __ldg(&cb[(size_t)code * DD + d]);
}

// ------------------------------------------------------------- loss finalize
__global__ void fin_kernel(float* __restrict__ loss) {
    double s = 0.0;
    for (int i = 0; i < BT / TM; ++i) s += g_partial[i];
    *loss = (float)(1.25 * s / (double)ZQ_ELEMS);   // (1 + BETA) * mean
}

// ---------------------------------------------------------------- launcher
extern "C" void kernel_launch(void* const* d_in, const int* in_sizes, int n_in,
                              void* d_out, int out_size) {
    const float* z  = (const float*)d_in[0];
    const float* cb = (const float*)d_in[1];
    float* out = (float*)d_out;

    float* zq     = out;
    float* codesF = nullptr;
    float* lossF  = nullptr;
    float* dist   = nullptr;
    if ((long long)out_size >= OUT_FULL) {
        codesF = out + ZQ_ELEMS;
        lossF  = codesF + BT;
        dist   = lossF + 1;
    }

    const int smem_bytes = (DD * TM + DD * CS_LD + TM) * (int)sizeof(float);
    cudaFuncSetAttribute(dist_kernel, cudaFuncAttributeMaxDynamicSharedMemorySize, smem_bytes);

    c2_kernel<<<(NCODES + 255) / 256, 256>>>(cb);
    dist_kernel<<<BT / TM, TPB, smem_bytes>>>(z, cb, dist, codesF);
    zq_kernel<<<ZQ_ELEMS / 256, 256>>>(cb, zq);
    if (lossF) fin_kernel<<<1, 1>>>(lossF);
}

// round 8
// speedup vs baseline: 1.5167x; 1.5167x over previous
#include <cuda_runtime.h>
#include <cuda_bf16.h>
#include <cstdint>

// VectorQuantizer: z (8,128,4096) f32, codebook (1024,128) f32.
// Output layout (confirmed): concatenated f32
//   [0)        z_q_out (B,D,T)   4,194,304
//   [4194304)  codes   (B,T)        32,768
//   [4227072)  loss                      1
//   [4227073)  dist    (B,T,1024) 33,554,432  (odd float offset: NOT 16B aligned)

#define DD      128
#define NCODES  1024
#define TT      4096
#define BB      8
#define BT      (BB*TT)          // 32768
#define ZQ_ELEMS (BB*DD*TT)
#define OUT_FULL (ZQ_ELEMS + BT + 1 + (long long)BT*NCODES)
#define PREPZ_SMEM (DD * 130 * 4)   // 66560 bytes (dynamic)

__device__ __align__(16) unsigned short g_zh[(size_t)BT*DD];   // bf16 hi, row-major [tok][d]
__device__ __align__(16) unsigned short g_zl[(size_t)BT*DD];   // bf16 lo
__device__ __align__(16) unsigned short g_ch[NCODES*DD];       // codebook hi [code][d]
__device__ __align__(16) unsigned short g_cl[NCODES*DD];
__device__ float  g_r2[BT];
__device__ float  g_c2[NCODES];
__device__ float  g_minv[BT*8];
__device__ int    g_mini[BT*8];
__device__ int    g_codes[BT];
__device__ double g_partial[256];

__device__ __forceinline__ uint32_t smem_u32(const void* p) {
    uint32_t a;
    asm("{ .reg .u64 t; cvta.to.shared.u64 t, %1; cvt.u32.u64 %0, t; }" : "=r"(a) : "l"(p));
    return a;
}
__device__ __forceinline__ uint32_t packbf(float x0, float x1) {
    unsigned short h0 = __bfloat16_as_ushort(__float2bfloat16(x0));
    unsigned short h1 = __bfloat16_as_ushort(__float2bfloat16(x1));
    return ((uint32_t)h1 << 16) | h0;
}

// --------------------------------------------------- prep z: split + transpose + r2
// dynamic smem: float stg[DD*130]
__global__ __launch_bounds__(128)
void prep_z(const float* __restrict__ z) {
    extern __shared__ float stg[];
    const int tid = threadIdx.x, bx = blockIdx.x;
    const int b = bx >> 5, t0 = (bx & 31) * 128;
    const float* zb = z + (size_t)b * DD * TT + t0;
    for (int idx = tid; idx < DD * 128; idx += 128) {
        int d = idx >> 7, tl = idx & 127;
        stg[d * 130 + tl] = zb[(size_t)d * TT + tl];
    }
    __syncthreads();
    const int tok = bx * 128 + tid;
    uint4* oh = (uint4*)(g_zh + (size_t)tok * DD);
    uint4* ol = (uint4*)(g_zl + (size_t)tok * DD);
    double r2 = 0.0;
    #pragma unroll 4
    for (int c = 0; c < 16; ++c) {
        uint32_t wh[4], wl[4];
        #pragma unroll
        for (int q = 0; q < 4; ++q) {
            float x0 = stg[(c * 8 + q * 2) * 130 + tid];
            float x1 = stg[(c * 8 + q * 2 + 1) * 130 + tid];
            r2 += (double)x0 * x0 + (double)x1 * x1;
            wh[q] = packbf(x0, x1);
            float e0 = x0 - __bfloat162float(__float2bfloat16(x0));
            float e1 = x1 - __bfloat162float(__float2bfloat16(x1));
            wl[q] = packbf(e0, e1);
        }
        oh[c] = make_uint4(wh[0], wh[1], wh[2], wh[3]);
        ol[c] = make_uint4(wl[0], wl[1], wl[2], wl[3]);
    }
    g_r2[tok] = (float)r2;
}

// --------------------------------------------------- prep codebook: split + c2
__global__ __launch_bounds__(128)
void prep_c(const float* __restrict__ cb) {
    const int code = blockIdx.x * 128 + threadIdx.x;
    const float* r = cb + (size_t)code * DD;
    uint4* oh = (uint4*)(g_ch + (size_t)code * DD);
    uint4* ol = (uint4*)(g_cl + (size_t)code * DD);
    double c2 = 0.0;
    #pragma unroll 4
    for (int c = 0; c < 16; ++c) {
        uint32_t wh[4], wl[4];
        #pragma unroll
        for (int q = 0; q < 4; ++q) {
            float x0 = r[c * 8 + q * 2], x1 = r[c * 8 + q * 2 + 1];
            c2 += (double)x0 * x0 + (double)x1 * x1;
            wh[q] = packbf(x0, x1);
            float e0 = x0 - __bfloat162float(__float2bfloat16(x0));
            float e1 = x1 - __bfloat162float(__float2bfloat16(x1));
            wl[q] = packbf(e0, e1);
        }
        oh[c] = make_uint4(wh[0], wh[1], wh[2], wh[3]);
        ol[c] = make_uint4(wl[0], wl[1], wl[2], wl[3]);
    }
    g_c2[code] = (float)c2;
}

// --------------------------------------------------- warp-MMA dist GEMM + partial argmin
// grid (256, 8): bx = 128-row tile, by = 128-code tile. 256 thr, 8 warps (2 x 4).
__global__ __launch_bounds__(256, 2)
void vq_gemm(float* __restrict__ dist) {
    __shared__ __align__(16) unsigned char smA[16384];   // 128 x 64 bf16, SW128 swizzled
    __shared__ __align__(16) unsigned char smB[16384];
    __shared__ float r2s[128], c2s[128];
    __shared__ float redV[128 * 4];
    __shared__ int   redI[128 * 4];

    const int tid = threadIdx.x, lane = tid & 31, wid = tid >> 5;
    const int wm = wid & 1, wn = wid >> 1;          // warp tile: rows wm*64, cols wn*32
    const int bx = blockIdx.x, by = blockIdx.y;
    const int rowbase = bx * 128;

    if (tid < 128) { r2s[tid] = g_r2[rowbase + tid]; c2s[tid] = g_c2[by * 128 + tid]; }

    const uint32_t uA = smem_u32(smA), uB = smem_u32(smB);
    float acc[4][4][4];
    #pragma unroll
    for (int i = 0; i < 4; ++i)
        #pragma unroll
        for (int j = 0; j < 4; ++j)
            #pragma unroll
            for (int k = 0; k < 4; ++k) acc[i][j][k] = 0.0f;

    #pragma unroll
    for (int seg = 0; seg < 3; ++seg) {
        const uint4* aSrc = (const uint4*)((seg == 1) ? g_zl : g_zh);
        const uint4* bSrc = (const uint4*)((seg == 2) ? g_cl : g_ch);
        #pragma unroll
        for (int kc = 0; kc < 2; ++kc) {
            const int k0u4 = kc * 8;     // uint4 offset within 128-elem row
            __syncthreads();
            #pragma unroll
            for (int i = 0; i < 4; ++i) {
                int idx = tid + i * 256;               // 0..1023
                int r = idx >> 3, kb = idx & 7;
                uint32_t byte = (uint32_t)r * 128 + kb * 16;
                uint32_t sw = byte ^ ((byte >> 3) & 0x70);
                *(uint4*)(smA + sw) = aSrc[(size_t)(rowbase + r) * 16 + k0u4 + kb];
                *(uint4*)(smB + sw) = bSrc[(size_t)(by * 128 + r) * 16 + k0u4 + kb];
            }
            __syncthreads();

            #pragma unroll
            for (int ks = 0; ks < 4; ++ks) {
                uint32_t a[4][4], b[4][2];
                #pragma unroll
                for (int mt = 0; mt < 4; ++mt) {
                    int row = wm * 64 + mt * 16 + (lane & 15);
                    int kcol = ks * 16 + (lane >> 4) * 8;
                    uint32_t byte = (uint32_t)row * 128 + kcol * 2;
                    uint32_t ad = uA + (byte ^ ((byte >> 3) & 0x70));
                    asm volatile("ldmatrix.sync.aligned.m8n8.x4.shared.b16 {%0,%1,%2,%3}, [%4];"
                        : "=r"(a[mt][0]), "=r"(a[mt][1]), "=r"(a[mt][2]), "=r"(a[mt][3]) : "r"(ad));
                }
                #pragma unroll
                for (int nt = 0; nt < 2; ++nt) {
                    // B stored [n][k] row-major == col-major KxN: NON-trans ldmatrix.
                    int n = wn * 32 + nt * 16 + ((lane >> 4) & 1) * 8 + (lane & 7);
                    int kcol = ks * 16 + ((lane >> 3) & 1) * 8;
                    uint32_t byte = (uint32_t)n * 128 + kcol * 2;
                    uint32_t ad = uB + (byte ^ ((byte >> 3) & 0x70));
                    asm volatile("ldmatrix.sync.aligned.m8n8.x4.shared.b16 {%0,%1,%2,%3}, [%4];"
                        : "=r"(b[nt * 2][0]), "=r"(b[nt * 2][1]),
                          "=r"(b[nt * 2 + 1][0]), "=r"(b[nt * 2 + 1][1]) : "r"(ad));
                }
                #pragma unroll
                for (int mt = 0; mt < 4; ++mt)
                    #pragma unroll
                    for (int nn = 0; nn < 4; ++nn)
                        asm volatile(
                            "mma.sync.aligned.m16n8k16.row.col.f32.bf16.bf16.f32 "
                            "{%0,%1,%2,%3}, {%4,%5,%6,%7}, {%8,%9}, {%0,%1,%2,%3};"
                            : "+f"(acc[mt][nn][0]), "+f"(acc[mt][nn][1]),
                              "+f"(acc[mt][nn][2]), "+f"(acc[mt][nn][3])
                            : "r"(a[mt][0]), "r"(a[mt][1]), "r"(a[mt][2]), "r"(a[mt][3]),
                              "r"(b[nn][0]), "r"(b[nn][1]));
            }
        }
    }

    // epilogue: dist = (r2 - 2*dot) + c2, stores + per-row argmin
    #pragma unroll
    for (int mt = 0; mt < 4; ++mt) {
        const int r0 = wm * 64 + mt * 16 + (lane >> 2);
        const int r1 = r0 + 8;
        const float r2a = r2s[r0], r2b = r2s[r1];
        float v0 = 3.4e38f, v1 = 3.4e38f; int i0 = 0, i1 = 0;
        float* dp0 = dist ? dist + (size_t)(rowbase + r0) * NCODES + by * 128 : nullptr;
        float* dp1 = dist ? dist + (size_t)(rowbase + r1) * NCODES + by * 128 : nullptr;
        #pragma unroll
        for (int nn = 0; nn < 4; ++nn) {
            const int cl0 = wn * 32 + nn * 8 + (lane & 3) * 2;   // local col 0..127
            const float c20 = c2s[cl0], c21 = c2s[cl0 + 1];
            float d00 = __fadd_rn(__fsub_rn(r2a, __fmul_rn(2.0f, acc[mt][nn][0])), c20);
            float d01 = __fadd_rn(__fsub_rn(r2a, __fmul_rn(2.0f, acc[mt][nn][1])), c21);
            float d10 = __fadd_rn(__fsub_rn(r2b, __fmul_rn(2.0f, acc[mt][nn][2])), c20);
            float d11 = __fadd_rn(__fsub_rn(r2b, __fmul_rn(2.0f, acc[mt][nn][3])), c21);
            if (dp0) { __stcs(dp0 + cl0, d00); __stcs(dp0 + cl0 + 1, d01);
                       __stcs(dp1 + cl0, d10); __stcs(dp1 + cl0 + 1, d11); }
            if (d00 < v0) { v0 = d00; i0 = cl0; }
            if (d01 < v0) { v0 = d01; i0 = cl0 + 1; }
            if (d10 < v1) { v1 = d10; i1 = cl0; }
            if (d11 < v1) { v1 = d11; i1 = cl0 + 1; }
        }
        #pragma unroll
        for (int off = 1; off <= 2; off <<= 1) {
            float ov = __shfl_xor_sync(0xffffffff, v0, off);
            int   oi = __shfl_xor_sync(0xffffffff, i0, off);
            if (ov < v0 || (ov == v0 && oi < i0)) { v0 = ov; i0 = oi; }
            ov = __shfl_xor_sync(0xffffffff, v1, off);
            oi = __shfl_xor_sync(0xffffffff, i1, off);
            if (ov < v1 || (ov == v1 && oi < i1)) { v1 = ov; i1 = oi; }
        }
        if ((lane & 3) == 0) {
            redV[r0 * 4 + wn] = v0; redI[r0 * 4 + wn] = i0;
            redV[r1 * 4 + wn] = v1; redI[r1 * 4 + wn] = i1;
        }
    }
    __syncthreads();
    if (tid < 128) {
        float bv = redV[tid * 4]; int bi = redI[tid * 4];
        #pragma unroll
        for (int w = 1; w < 4; ++w) {
            float v = redV[tid * 4 + w]; int ii = redI[tid * 4 + w];
            if (v < bv || (v == bv && ii < bi)) { bv = v; bi = ii; }
        }
        g_minv[(size_t)(rowbase + tid) * 8 + by] = bv;
        g_mini[(size_t)(rowbase + tid) * 8 + by] = by * 128 + bi;
    }
}

// --------------------------------------------------- cross-chunk argmin + loss partials
__global__ __launch_bounds__(128)
void combine(float* __restrict__ codesF) {
    __shared__ double s[128];
    const int tid = threadIdx.x;
    const int row = blockIdx.x * 128 + tid;
    float bv = g_minv[(size_t)row * 8]; int bi = g_mini[(size_t)row * 8];
    #pragma unroll
    for (int c = 1; c < 8; ++c) {
        float v = g_minv[(size_t)row * 8 + c]; int ii = g_mini[(size_t)row * 8 + c];
        if (v < bv || (v == bv && ii < bi)) { bv = v; bi = ii; }
    }
    g_codes[row] = bi;
    if (codesF) codesF[row] = (float)bi;
    s[tid] = (double)bv;
    __syncthreads();
    for (int o = 64; o; o >>= 1) {
        if (tid < o) s[tid] += s[tid + o];
        __syncthreads();
    }
    if (tid == 0) g_partial[blockIdx.x] = s[0];
}

// --------------------------------------------------- z_q gather (B,D,T)
__global__ void zq_kernel(const float* __restrict__ cb, float* __restrict__ zq) {
    int idx = blockIdx.x * blockDim.x + threadIdx.x;
    int t = idx & (TT - 1);
    int d = (idx >> 12) & (DD - 1);
    int b = idx >> 19;
    int code = g_codes[(b << 12) + t];
    zq[idx] = __ldg(&cb[(size_t)code * DD + d]);
}

// --------------------------------------------------- loss finalize
__global__ void fin_kernel(float* __restrict__ loss) {
    __shared__ double s[256];
    s[threadIdx.x] = g_partial[threadIdx.x];
    __syncthreads();
    for (int o = 128; o; o >>= 1) {
        if (threadIdx.x < o) s[threadIdx.x] += s[threadIdx.x + o];
        __syncthreads();
    }
    if (threadIdx.x == 0) *loss = (float)(1.25 * s[0] / (double)ZQ_ELEMS);
}

// --------------------------------------------------- launcher
extern "C" void kernel_launch(void* const* d_in, const int* in_sizes, int n_in,
                              void* d_out, int out_size) {
    const float* z  = (const float*)d_in[0];
    const float* cb = (const float*)d_in[1];
    float* out = (float*)d_out;

    float* zq     = out;
    float* codesF = nullptr;
    float* lossF  = nullptr;
    float* dist   = nullptr;
    if ((long long)out_size >= OUT_FULL) {
        codesF = out + ZQ_ELEMS;
        lossF  = codesF + BT;
        dist   = lossF + 1;
    }

    cudaFuncSetAttribute(prep_z, cudaFuncAttributeMaxDynamicSharedMemorySize, PREPZ_SMEM);

    prep_z<<<256, 128, PREPZ_SMEM>>>(z);
    prep_c<<<8, 128>>>(cb);
    vq_gemm<<<dim3(256, 8), 256>>>(dist);
    combine<<<256, 128>>>(codesF);
    zq_kernel<<<ZQ_ELEMS / 256, 256>>>(cb, zq);
    if (lossF) fin_kernel<<<1, 256>>>(lossF);
}